// round 1
// baseline (speedup 1.0000x reference)
#include <cuda_runtime.h>

#define CHANNELS  8
#define IN_CH     8
#define NPARAMS   169      // 80 + 64 + 8 + 8 + 8 + 1
#define H_        128
#define W_        192
#define HW_       (H_ * W_)
#define GI        8        // instances per block in the head kernel
#define MAX_INST  128

// Logits scratch: 128 inst * 128 * 192 * 4B = 12.6 MB (L2-resident on GB300)
__device__ float g_logits[MAX_INST * HW_];

// ---------------------------------------------------------------------------
// Kernel 1: dynamic mask head MLP. One thread = one pixel, GI instances/block.
// ---------------------------------------------------------------------------
__global__ __launch_bounds__(256)
void mask_head_kernel(const float* __restrict__ mask_feats,   // (N, 8, H, W)
                      const float* __restrict__ params,       // (n_inst, 169)
                      const float* __restrict__ inst_loc,     // (n_inst, 2)
                      const float* __restrict__ soi_tab,      // (6,)
                      const int*   __restrict__ im_inds,      // (n_inst,)
                      const int*   __restrict__ fpn_levels,   // (n_inst,)
                      int n_inst)
{
    __shared__ float sp[GI * NPARAMS];
    __shared__ float s_ix[GI], s_iy[GI], s_isoi[GI];
    __shared__ int   s_im[GI];

    const int n0  = blockIdx.y * GI;
    const int tid = threadIdx.x;

    // Stage params for GI instances into shared memory
    const int npar = min(GI, n_inst - n0) * NPARAMS;
    for (int i = tid; i < npar; i += blockDim.x)
        sp[i] = params[(size_t)n0 * NPARAMS + i];
    if (tid < GI && n0 + tid < n_inst) {
        int n = n0 + tid;
        s_ix[tid]   = inst_loc[2 * n + 0];
        s_iy[tid]   = inst_loc[2 * n + 1];
        s_isoi[tid] = 1.0f / soi_tab[fpn_levels[n]];
        s_im[tid]   = im_inds[n];
    }
    __syncthreads();

    const int p  = blockIdx.x * blockDim.x + tid;   // pixel index, HW_ % 256 == 0
    const int px = p % W_;
    const int py = p / W_;
    const float lx = (float)px * 8.0f + 4.0f;       // MASK_FEAT_STRIDE = 8
    const float ly = (float)py * 8.0f + 4.0f;

    const int g_end = min(GI, n_inst - n0);
    #pragma unroll 1
    for (int g = 0; g < g_end; g++) {
        const float* prm = sp + g * NPARAMS;
        const float* f   = mask_feats + (size_t)s_im[g] * IN_CH * HW_ + p;

        const float rx = (s_ix[g] - lx) * s_isoi[g];
        const float ry = (s_iy[g] - ly) * s_isoi[g];

        float feat[IN_CH];
        #pragma unroll
        for (int c = 0; c < IN_CH; c++) feat[c] = f[(size_t)c * HW_];

        // layer 0: 8 x 10, ReLU
        float h0[CHANNELS];
        #pragma unroll
        for (int o = 0; o < CHANNELS; o++) {
            float a = prm[152 + o];                  // b0
            a = fmaf(prm[o * 10 + 0], rx, a);
            a = fmaf(prm[o * 10 + 1], ry, a);
            #pragma unroll
            for (int c = 0; c < IN_CH; c++)
                a = fmaf(prm[o * 10 + 2 + c], feat[c], a);
            h0[o] = fmaxf(a, 0.0f);
        }

        // layer 1: 8 x 8, ReLU
        float h1[CHANNELS];
        #pragma unroll
        for (int o = 0; o < CHANNELS; o++) {
            float a = prm[160 + o];                  // b1
            #pragma unroll
            for (int c = 0; c < CHANNELS; c++)
                a = fmaf(prm[80 + o * 8 + c], h0[c], a);
            h1[o] = fmaxf(a, 0.0f);
        }

        // layer 2: 1 x 8
        float a = prm[168];                          // b2
        #pragma unroll
        for (int c = 0; c < CHANNELS; c++)
            a = fmaf(prm[144 + c], h1[c], a);

        g_logits[(size_t)(n0 + g) * HW_ + p] = a;
    }
}

// ---------------------------------------------------------------------------
// Kernel 2: aligned 2x bilinear upsample. One thread = one 2x2 output block.
//   O[2r,  2c  ] = 0.25*(L[r-1,c-1] + L[r-1,c] + L[r,c-1] + L[r,c])
//   O[2r,  2c+1] = 0.5 *(L[r-1,c]   + L[r,c])
//   O[2r+1,2c  ] = 0.5 *(L[r,c-1]   + L[r,c])
//   O[2r+1,2c+1] =       L[r,c]
// (indices clamped at 0; derived from pad-edge + align-corners interp + crop)
// ---------------------------------------------------------------------------
__global__ __launch_bounds__(256)
void upsample_kernel(float* __restrict__ out, int n_inst)
{
    const int idx = blockIdx.x * blockDim.x + threadIdx.x;
    if (idx >= n_inst * HW_) return;

    const int c = idx % W_;
    const int r = (idx / W_) % H_;
    const int n = idx / HW_;

    const float* Ln = g_logits + (size_t)n * HW_;
    const int cm = max(c - 1, 0);
    const int rm = max(r - 1, 0);

    const float v00 = Ln[rm * W_ + cm];
    const float v01 = Ln[rm * W_ + c];
    const float v10 = Ln[r  * W_ + cm];
    const float v11 = Ln[r  * W_ + c];

    float2 row0 = make_float2(0.25f * ((v00 + v01) + (v10 + v11)),
                              0.5f  * (v01 + v11));
    float2 row1 = make_float2(0.5f  * (v10 + v11), v11);

    float* o = out + (size_t)n * (4 * HW_) + (2 * r) * (2 * W_) + 2 * c;
    *reinterpret_cast<float2*>(o)            = row0;
    *reinterpret_cast<float2*>(o + 2 * W_)   = row1;
}

// ---------------------------------------------------------------------------
extern "C" void kernel_launch(void* const* d_in, const int* in_sizes, int n_in,
                              void* d_out, int out_size)
{
    const float* mask_feats = (const float*)d_in[0];
    const float* params     = (const float*)d_in[1];
    const float* inst_loc   = (const float*)d_in[2];
    const float* soi_tab    = (const float*)d_in[3];
    const int*   im_inds    = (const int*)d_in[4];
    const int*   fpn_levels = (const int*)d_in[5];
    float*       out        = (float*)d_out;

    const int n_inst = in_sizes[1] / NPARAMS;   // 128

    dim3 grid1(HW_ / 256, (n_inst + GI - 1) / GI);
    mask_head_kernel<<<grid1, 256>>>(mask_feats, params, inst_loc, soi_tab,
                                     im_inds, fpn_levels, n_inst);

    const int total = n_inst * HW_;
    upsample_kernel<<<(total + 255) / 256, 256>>>(out, n_inst);
}

// round 2
// speedup vs baseline: 2.0968x; 2.0968x over previous
#include <cuda_runtime.h>

#define CHANNELS  8
#define IN_CH     8
#define NPARAMS   169      // 80 + 64 + 8 + 8 + 8 + 1
#define H_        128
#define W_        192
#define HW_       (H_ * W_)
#define GI        4        // instances per block in the head kernel
#define MAX_INST  128

// Logits scratch: 128 * 24576 * 4B = 12.6 MB (L2-resident on GB300)
__device__ float g_logits[MAX_INST * HW_];

typedef unsigned long long u64;

// ---- packed fp32x2 helpers (Blackwell) -------------------------------------
__device__ __forceinline__ u64 fma2(u64 a, u64 b, u64 c) {
    u64 d;
    asm("fma.rn.f32x2 %0, %1, %2, %3;" : "=l"(d) : "l"(a), "l"(b), "l"(c));
    return d;
}
__device__ __forceinline__ u64 pack2(float lo, float hi) {
    u64 d;
    asm("mov.b64 %0, {%1, %2};" : "=l"(d) : "f"(lo), "f"(hi));
    return d;
}
__device__ __forceinline__ void unpack2(u64 v, float& lo, float& hi) {
    asm("mov.b64 {%0, %1}, %2;" : "=f"(lo), "=f"(hi) : "l"(v));
}
__device__ __forceinline__ u64 relu2(u64 v) {
    float lo, hi;
    unpack2(v, lo, hi);
    return pack2(fmaxf(lo, 0.0f), fmaxf(hi, 0.0f));
}

// ---------------------------------------------------------------------------
// Kernel 1: dynamic mask head MLP.
// One thread = 4 consecutive pixels (2x f32x2), GI instances per block.
// Weights staged in shared memory PRE-DUPLICATED (float2{w,w}) so each use is
// a single broadcast LDS.64 giving a packed operand for fma.rn.f32x2.
// ---------------------------------------------------------------------------
__global__ __launch_bounds__(256)
void mask_head_kernel(const float* __restrict__ mask_feats,   // (N, 8, H, W)
                      const float* __restrict__ params,       // (n_inst, 169)
                      const float* __restrict__ inst_loc,     // (n_inst, 2)
                      const float* __restrict__ soi_tab,      // (6,)
                      const int*   __restrict__ im_inds,      // (n_inst,)
                      const int*   __restrict__ fpn_levels,   // (n_inst,)
                      int n_inst)
{
    __shared__ float2 sp2[GI * NPARAMS];
    __shared__ float  s_ix[GI], s_iy[GI], s_isoi[GI];
    __shared__ int    s_im[GI];

    const int n0  = blockIdx.y * GI;
    const int tid = threadIdx.x;

    // Stage duplicated params for GI instances (params are contiguous rows)
    const int g_cnt = min(GI, n_inst - n0);
    for (int i = tid; i < g_cnt * NPARAMS; i += 256) {
        float v = params[(size_t)n0 * NPARAMS + i];
        sp2[i] = make_float2(v, v);
    }
    if (tid < GI && n0 + tid < n_inst) {
        int n = n0 + tid;
        s_ix[tid]   = inst_loc[2 * n + 0];
        s_iy[tid]   = inst_loc[2 * n + 1];
        s_isoi[tid] = 1.0f / soi_tab[fpn_levels[n]];
        s_im[tid]   = im_inds[n];
    }
    __syncthreads();

    const int p0 = (blockIdx.x * 256 + tid) * 4;   // 4 consecutive px, same row
    const int px = p0 % W_;
    const int py = p0 / W_;
    const float lx0 = (float)px * 8.0f + 4.0f;     // MASK_FEAT_STRIDE = 8
    const float ly  = (float)py * 8.0f + 4.0f;

    #pragma unroll 1
    for (int g = 0; g < g_cnt; g++) {
        const u64* prm = reinterpret_cast<const u64*>(sp2) + g * NPARAMS;

        const float s  = s_isoi[g];
        const float dx = s_ix[g] - lx0;
        const float ryv = (s_iy[g] - ly) * s;
        const u64 rx01 = pack2(dx * s,            (dx - 8.0f)  * s);
        const u64 rx23 = pack2((dx - 16.0f) * s,  (dx - 24.0f) * s);
        const u64 ry   = pack2(ryv, ryv);

        // Load 8 feature channels for 4 pixels (float4 each)
        const float4* f4 = reinterpret_cast<const float4*>(
            mask_feats + (size_t)s_im[g] * IN_CH * HW_ + p0);
        u64 fp01[IN_CH], fp23[IN_CH];
        #pragma unroll
        for (int c = 0; c < IN_CH; c++) {
            float4 v = f4[c * (HW_ / 4)];
            fp01[c] = pack2(v.x, v.y);
            fp23[c] = pack2(v.z, v.w);
        }

        // layer 0: 8 x 10, ReLU
        u64 h01[CHANNELS], h23[CHANNELS];
        #pragma unroll
        for (int o = 0; o < CHANNELS; o++) {
            u64 b  = prm[152 + o];
            u64 a0 = b, a1 = b;
            u64 wx = prm[o * 10 + 0];
            u64 wy = prm[o * 10 + 1];
            a0 = fma2(wx, rx01, a0);  a1 = fma2(wx, rx23, a1);
            a0 = fma2(wy, ry,   a0);  a1 = fma2(wy, ry,   a1);
            #pragma unroll
            for (int c = 0; c < IN_CH; c++) {
                u64 w = prm[o * 10 + 2 + c];
                a0 = fma2(w, fp01[c], a0);
                a1 = fma2(w, fp23[c], a1);
            }
            h01[o] = relu2(a0);
            h23[o] = relu2(a1);
        }

        // layer 1: 8 x 8, ReLU
        u64 q01[CHANNELS], q23[CHANNELS];
        #pragma unroll
        for (int o = 0; o < CHANNELS; o++) {
            u64 b  = prm[160 + o];
            u64 a0 = b, a1 = b;
            #pragma unroll
            for (int c = 0; c < CHANNELS; c++) {
                u64 w = prm[80 + o * 8 + c];
                a0 = fma2(w, h01[c], a0);
                a1 = fma2(w, h23[c], a1);
            }
            q01[o] = relu2(a0);
            q23[o] = relu2(a1);
        }

        // layer 2: 1 x 8
        u64 b  = prm[168];
        u64 a0 = b, a1 = b;
        #pragma unroll
        for (int c = 0; c < CHANNELS; c++) {
            u64 w = prm[144 + c];
            a0 = fma2(w, q01[c], a0);
            a1 = fma2(w, q23[c], a1);
        }

        float o0, o1, o2, o3;
        unpack2(a0, o0, o1);
        unpack2(a1, o2, o3);
        *reinterpret_cast<float4*>(g_logits + (size_t)(n0 + g) * HW_ + p0) =
            make_float4(o0, o1, o2, o3);
    }
}

// ---------------------------------------------------------------------------
// Kernel 2: aligned 2x bilinear upsample.
// One thread = 2 input px (one row) -> 2x4 output px as two float4 stores.
//   O[2r,  2c  ] = 0.25*(L[r-1,c-1] + L[r-1,c] + L[r,c-1] + L[r,c])
//   O[2r,  2c+1] = 0.5 *(L[r-1,c]   + L[r,c])
//   O[2r+1,2c  ] = 0.5 *(L[r,c-1]   + L[r,c])
//   O[2r+1,2c+1] =       L[r,c]          (r-1, c-1 clamped at 0)
// ---------------------------------------------------------------------------
__global__ __launch_bounds__(256)
void upsample_kernel(float* __restrict__ out, int n_inst)
{
    const int idx = blockIdx.x * 256 + threadIdx.x;
    if (idx >= n_inst * (HW_ / 2)) return;

    const int c2 = idx % (W_ / 2);
    const int r  = (idx / (W_ / 2)) % H_;
    const int n  = idx / (HW_ / 2);

    const float* Ln = g_logits + (size_t)n * HW_;
    const int c0 = 2 * c2;
    const int cm = max(c0 - 1, 0);
    const int rm = max(r - 1, 0);

    const float  tm  = Ln[rm * W_ + cm];
    const float2 t01 = *reinterpret_cast<const float2*>(Ln + rm * W_ + c0);
    const float  um  = Ln[r * W_ + cm];
    const float2 u01 = *reinterpret_cast<const float2*>(Ln + r * W_ + c0);

    float4 row0, row1;
    row0.x = 0.25f * ((tm + t01.x) + (um + u01.x));
    row0.y = 0.5f  * (t01.x + u01.x);
    row0.z = 0.25f * ((t01.x + t01.y) + (u01.x + u01.y));
    row0.w = 0.5f  * (t01.y + u01.y);
    row1.x = 0.5f  * (um + u01.x);
    row1.y = u01.x;
    row1.z = 0.5f  * (u01.x + u01.y);
    row1.w = u01.y;

    float* o = out + (size_t)n * (4 * HW_) + (2 * r) * (2 * W_) + 4 * c2;
    *reinterpret_cast<float4*>(o)          = row0;
    *reinterpret_cast<float4*>(o + 2 * W_) = row1;
}

// ---------------------------------------------------------------------------
extern "C" void kernel_launch(void* const* d_in, const int* in_sizes, int n_in,
                              void* d_out, int out_size)
{
    const float* mask_feats = (const float*)d_in[0];
    const float* params     = (const float*)d_in[1];
    const float* inst_loc   = (const float*)d_in[2];
    const float* soi_tab    = (const float*)d_in[3];
    const int*   im_inds    = (const int*)d_in[4];
    const int*   fpn_levels = (const int*)d_in[5];
    float*       out        = (float*)d_out;

    const int n_inst = in_sizes[1] / NPARAMS;   // 128

    dim3 grid1(HW_ / (256 * 4), (n_inst + GI - 1) / GI);   // 24 x 32
    mask_head_kernel<<<grid1, 256>>>(mask_feats, params, inst_loc, soi_tab,
                                     im_inds, fpn_levels, n_inst);

    const int total2 = n_inst * (HW_ / 2);
    upsample_kernel<<<(total2 + 255) / 256, 256>>>(out, n_inst);
}